// round 9
// baseline (speedup 1.0000x reference)
#include <cuda_runtime.h>
#include <cstdint>
#include <cstddef>

#define NCH    64
#define OCH    64
#define CONVCH 4096
#define HH     56
#define WW     56
#define PLANE  (HH*WW)     // 3136
#define NPIX   14
#define TROW   58          // full plane + 2 halo rows
#define SEGW   20          // smem segment stride: 16 data + 4 pad floats
#define TCOL   84          // 4*SEGW + 4 row pad: gives uniform bank tiling for LDS.128
#define PROW   64          // packed gmem row: 4 segments * 16 floats (dup boundaries)
#define NREF   128
#define NTHR   128
#define NACT   112         // 28 row-pairs * 4 segments
#define NJOB   (TROW*16)   // 928 float4 fill jobs per tile
#define TILEF  (TROW*TCOL) // 4872 floats per buffer

// Padded + boundary-duplicated copy of x: [8*64 planes][58 rows][64 floats].
// Segment t of each row holds plane cols 14t-1 .. 14t+14 (halo -> 0).
__device__ float xpack[8 * NCH * TROW * PROW];   // 7.6 MB

__device__ __forceinline__ void cp_async16(void* dst, const void* src) {
    unsigned d = (unsigned)__cvta_generic_to_shared(dst);
    asm volatile("cp.async.cg.shared.global [%0], [%1], 16;\n" :: "r"(d), "l"(src));
}
__device__ __forceinline__ void cp_commit() { asm volatile("cp.async.commit_group;\n" ::: "memory"); }
__device__ __forceinline__ void cp_wait0()  { asm volatile("cp.async.wait_group 0;\n" ::: "memory"); }

__global__ __launch_bounds__(256)
void pad_kernel(const float* __restrict__ x) {
    const int plane = blockIdx.x;                 // b*64 + ic
    const float* xp = x + (size_t)plane * PLANE;
    float* dst = xpack + (size_t)plane * (TROW * PROW);
    for (int i = threadIdx.x; i < TROW * PROW; i += blockDim.x) {
        int r = i >> 6, c = i & 63;
        int t = c >> 4, j = c & 15;
        int pr = r - 1, pc = 14*t - 1 + j;
        float v = 0.f;
        if (pr >= 0 && pr < HH && pc >= 0 && pc < WW) v = xp[pr*WW + pc];
        dst[i] = v;
    }
}

__global__ __launch_bounds__(NTHR, 4)
void prcn_kernel(const float* __restrict__ Wt,      // [4096,9]
                 const float* __restrict__ bias,    // [4096]
                 const void*  __restrict__ index_raw, // int32 or int64 [8192]
                 float* __restrict__ out)           // [8,64,56,56]
{
    __shared__ float tile[2][TROW][TCOL];   // 38976 B double buffer
    __shared__ float wsm[NREF][10];
    __shared__ int   cidx[NREF];

    const int tid = threadIdx.x;
    const int o   = blockIdx.x & 63;
    const int b   = blockIdx.x >> 6;

    // --- index dtype detection: int32 (JAX x64 off) vs int64 ---
    const int* idx32 = (const int*)index_raw;
    const bool is64 = ((idx32[1] | idx32[3] | idx32[5] | idx32[7]) == 0);

    if (tid < NREF) {
        int v = is64 ? (int)((const long long*)index_raw)[o*NREF + tid]
                     : idx32[o*NREF + tid];
        cidx[tid] = v & (CONVCH - 1);
    }
    // Zero both buffers once: fills rewrite only the 16-float data runs of each
    // segment; segment pads (pos 16..19) and row pads (cols 80..83) stay zero.
    for (int j = tid; j < 2*TILEF; j += NTHR) ((float*)tile)[j] = 0.f;
    __syncthreads();
    for (int j = tid; j < NREF*10; j += NTHR) {
        int k = j / 10, l = j - k*10;
        int c = cidx[k];
        wsm[k][l] = (l < 9) ? Wt[c*9 + l] : bias[c];
    }
    __syncthreads();

    // Fill-job geometry: job j copies float4 #j of the packed plane into smem.
    //   src float offset = 4*j   (contiguous in xpack)
    //   dst float offset = (j>>4)*TCOL + ((j>>2)&3)*SEGW + (j&3)*4
    int doff[8];
    #pragma unroll
    for (int m = 0; m < 8; m++) {
        int j = tid + m*NTHR;
        doff[m] = (j >> 4)*TCOL + ((j >> 2) & 3)*SEGW + (j & 3)*4;
    }
    const bool job7 = (tid + 7*NTHR) < NJOB;   // 928 = 7*128 + 32

    const int tr = tid >> 2;        // row-pair index 0..27 (tid < NACT)
    const int tx = tid & 3;         // segment index

    // Prologue: fill(0)
    {
        const float* xp = xpack + (size_t)(b*NCH + (cidx[0] >> 6)) * (TROW*PROW);
        float* Tb = &tile[0][0][0];
        #pragma unroll
        for (int m = 0; m < 7; m++) cp_async16(Tb + doff[m], xp + 4*(tid + m*NTHR));
        if (job7) cp_async16(Tb + doff[7], xp + 4*(tid + 7*NTHR));
        cp_commit();
    }

    float acc0[NPIX], acc1[NPIX], mx0[NPIX], mx1[NPIX];
    #pragma unroll
    for (int p = 0; p < NPIX; p++) { acc0[p] = 0.f; acc1[p] = 0.f; }

    for (int k = 0; k < NREF; k++) {
        cp_wait0();          // fill(k) landed (this thread's part)
        __syncthreads();     // landed everywhere; compute(k-1) done everywhere

        if (k + 1 < NREF) {  // fill(k+1) overlaps compute(k)
            const float* xp = xpack + (size_t)(b*NCH + (cidx[k+1] >> 6)) * (TROW*PROW);
            float* Tb = &tile[(k+1) & 1][0][0];
            #pragma unroll
            for (int m = 0; m < 7; m++) cp_async16(Tb + doff[m], xp + 4*(tid + m*NTHR));
            if (job7) cp_async16(Tb + doff[7], xp + 4*(tid + 7*NTHR));
            cp_commit();
        }

        if (tid < NACT) {
            float wv[10];
            #pragma unroll
            for (int l = 0; l < 10; l++) wv[l] = wsm[k][l];

            float s0[NPIX], s1[NPIX];
            #pragma unroll
            for (int p = 0; p < NPIX; p++) { s0[p] = wv[9]; s1[p] = wv[9]; }

            // 4-row window over segment tx: v[i] = plane col 14*tx - 1 + i.
            // Output row A (plane 2tr)   <- window rows 0,1,2
            // Output row B (plane 2tr+1) <- window rows 1,2,3
            #pragma unroll
            for (int ky = 0; ky < 4; ky++) {
                const float4* qp = (const float4*)&tile[k & 1][2*tr + ky][tx*SEGW];
                float4 q0 = qp[0], q1 = qp[1], q2 = qp[2], q3 = qp[3];
                float v[16] = {q0.x,q0.y,q0.z,q0.w, q1.x,q1.y,q1.z,q1.w,
                               q2.x,q2.y,q2.z,q2.w, q3.x,q3.y,q3.z,q3.w};
                if (ky < 3) {
                    const float w0 = wv[3*ky], w1 = wv[3*ky+1], w2 = wv[3*ky+2];
                    #pragma unroll
                    for (int p = 0; p < NPIX; p++)
                        s0[p] += w0*v[p] + w1*v[p+1] + w2*v[p+2];
                }
                if (ky > 0) {
                    const float w0 = wv[3*(ky-1)], w1 = wv[3*(ky-1)+1], w2 = wv[3*(ky-1)+2];
                    #pragma unroll
                    for (int p = 0; p < NPIX; p++)
                        s1[p] += w0*v[p] + w1*v[p+1] + w2*v[p+2];
                }
            }

            if ((k & 7) == 0) {
                #pragma unroll
                for (int p = 0; p < NPIX; p++) { mx0[p] = s0[p]; mx1[p] = s1[p]; }
            } else {
                #pragma unroll
                for (int p = 0; p < NPIX; p++) {
                    mx0[p] = fmaxf(mx0[p], s0[p]);
                    mx1[p] = fmaxf(mx1[p], s1[p]);
                }
            }
            if ((k & 7) == 7) {
                #pragma unroll
                for (int p = 0; p < NPIX; p++) { acc0[p] += mx0[p]; acc1[p] += mx1[p]; }
            }
        }
    }

    if (tid < NACT) {
        float* op = out + ((size_t)(b*OCH + o)*HH + 2*tr)*WW + tx*NPIX;
        #pragma unroll
        for (int p = 0; p < NPIX; p++) op[p]      = acc0[p] * 0.0625f;
        #pragma unroll
        for (int p = 0; p < NPIX; p++) op[WW + p] = acc1[p] * 0.0625f;
    }
}

extern "C" void kernel_launch(void* const* d_in, const int* in_sizes, int n_in,
                              void* d_out, int out_size) {
    const float* x    = (const float*)d_in[0];
    const float* Wt   = (const float*)d_in[1];
    const float* bias = (const float*)d_in[2];
    const void*  idx  = (const void*)d_in[3];
    float* out = (float*)d_out;
    pad_kernel<<<8 * NCH, 256>>>(x);
    prcn_kernel<<<OCH * 8, NTHR>>>(Wt, bias, idx, out);
}

// round 10
// speedup vs baseline: 1.3090x; 1.3090x over previous
#include <cuda_runtime.h>
#include <cstdint>
#include <cstddef>

#define NCH    64
#define OCH    64
#define CONVCH 4096
#define HH     56
#define WW     56
#define PLANE  (HH*WW)     // 3136
#define NPIX   14
#define TROW   58          // full plane + 2 halo rows
#define TCOL   68          // row stride; fill rows 16B aligned; LDS.64 conflict-free
#define NREF   128
#define NTHR   128
#define NACT   112         // 28 row-pairs * 4 col strips
#define NJOB   (HH*14)     // 784 float4 fill jobs

typedef unsigned long long ull;

__device__ __forceinline__ ull pk2(float lo, float hi) {
    ull r; asm("mov.b64 %0, {%1, %2};" : "=l"(r) : "f"(lo), "f"(hi)); return r;
}
__device__ __forceinline__ float2 up2(ull p) {
    float2 r; asm("mov.b64 {%0, %1}, %2;" : "=f"(r.x), "=f"(r.y) : "l"(p)); return r;
}
__device__ __forceinline__ ull f2fma(ull a, ull b, ull c) {   // packed 2xFMA
    ull d; asm("fma.rn.f32x2 %0, %1, %2, %3;" : "=l"(d) : "l"(a), "l"(b), "l"(c)); return d;
}

__device__ __forceinline__ void cp_async16(void* dst, const void* src) {
    unsigned d = (unsigned)__cvta_generic_to_shared(dst);
    asm volatile("cp.async.cg.shared.global [%0], [%1], 16;\n" :: "r"(d), "l"(src));
}
__device__ __forceinline__ void cp_commit() { asm volatile("cp.async.commit_group;\n" ::: "memory"); }
__device__ __forceinline__ void cp_wait0()  { asm volatile("cp.async.wait_group 0;\n" ::: "memory"); }

__global__ __launch_bounds__(NTHR, 4)
void prcn_kernel(const float* __restrict__ x,
                 const float* __restrict__ Wt,      // [4096,9]
                 const float* __restrict__ bias,    // [4096]
                 const void*  __restrict__ index_raw, // int32 or int64 [8192]
                 float* __restrict__ out)           // [8,64,56,56]
{
    __shared__ float tile[2][TROW][TCOL];   // 31552 B double buffer
    __shared__ float wsm[NREF][10];
    __shared__ int   cidx[NREF];

    const int tid = threadIdx.x;
    const int o   = blockIdx.x & 63;
    const int b   = blockIdx.x >> 6;

    // --- index dtype detection: int32 (JAX x64 off) vs int64 ---
    const int* idx32 = (const int*)index_raw;
    const bool is64 = ((idx32[1] | idx32[3] | idx32[5] | idx32[7]) == 0);

    if (tid < NREF) {
        int v = is64 ? (int)((const long long*)index_raw)[o*NREF + tid]
                     : idx32[o*NREF + tid];
        cidx[tid] = v & (CONVCH - 1);
    }
    // Zero both buffers once. Fills rewrite rows 1..56, cols [4,59] every
    // channel; halo rows 0,57 and cols 0..3 / 60..67 stay zero forever.
    for (int j = tid; j < 2*TROW*TCOL; j += NTHR) ((float*)tile)[j] = 0.f;
    __syncthreads();
    for (int j = tid; j < NREF*10; j += NTHR) {
        int k = j / 10, l = j - k*10;
        int c = cidx[k];
        wsm[k][l] = (l < 9) ? Wt[c*9 + l] : bias[c];
    }
    __syncthreads();

    // Fill-job geometry (identical to R8): job j -> row rr=j/14, col cc=(j%14)*4.
    int doff[7], soff[7];
    #pragma unroll
    for (int m = 0; m < 7; m++) {
        int j = tid + m*NTHR;
        int rr = j / 14, cc = (j - rr*14) * 4;
        doff[m] = (rr + 1)*TCOL + cc + 4;
        soff[m] = rr*WW + cc;
    }
    const bool job6 = (tid + 6*NTHR) < NJOB;

    const int tr = tid >> 2;        // row-pair index 0..27 (tid < NACT)
    const int tx = tid & 3;
    const int ubase = 14*tx + 2;    // even smem col; u[i] = plane col 14tx-2+i

    // Prologue: fill(0)
    {
        const float* xp = x + (size_t)(b*NCH + (cidx[0] >> 6)) * PLANE;
        float* Tb = &tile[0][0][0];
        #pragma unroll
        for (int m = 0; m < 6; m++) cp_async16(Tb + doff[m], xp + soff[m]);
        if (job6) cp_async16(Tb + doff[6], xp + soff[6]);
        cp_commit();
    }

    float acc0[NPIX], acc1[NPIX], mx0[NPIX], mx1[NPIX];
    #pragma unroll
    for (int p = 0; p < NPIX; p++) { acc0[p] = 0.f; acc1[p] = 0.f; }

    for (int k = 0; k < NREF; k++) {
        cp_wait0();
        __syncthreads();

        if (k + 1 < NREF) {
            const float* xp = x + (size_t)(b*NCH + (cidx[k+1] >> 6)) * PLANE;
            float* Tb = &tile[(k+1) & 1][0][0];
            #pragma unroll
            for (int m = 0; m < 6; m++) cp_async16(Tb + doff[m], xp + soff[m]);
            if (job6) cp_async16(Tb + doff[6], xp + soff[6]);
            cp_commit();
        }

        if (tid < NACT) {
            const float* wp = wsm[k];
            const ull BP = pk2(wp[9], wp[9]);
            ull SA[7], SB[7];
            #pragma unroll
            for (int j = 0; j < 7; j++) { SA[j] = BP; SB[j] = BP; }

            // 4-row window, pixel-pair packed f32x2 conv.
            // v[i] = u[i+1]; E_j=(v2j,v2j+1)=(hi UP[j], lo UP[j+1]); O_j=UP[j+1].
            #pragma unroll
            for (int ky = 0; ky < 4; ky++) {
                const ull* rp = (const ull*)&tile[k & 1][2*tr + ky][ubase];
                ull UP[9];
                #pragma unroll
                for (int m = 0; m < 9; m++) UP[m] = rp[m];
                ull E[8];
                #pragma unroll
                for (int j = 0; j < 8; j++) {
                    float2 a = up2(UP[j]), c = up2(UP[j+1]);
                    E[j] = pk2(a.y, c.x);
                }
                if (ky < 3) {
                    const ull w0 = pk2(wp[3*ky],   wp[3*ky]);
                    const ull w1 = pk2(wp[3*ky+1], wp[3*ky+1]);
                    const ull w2 = pk2(wp[3*ky+2], wp[3*ky+2]);
                    #pragma unroll
                    for (int j = 0; j < 7; j++)
                        SA[j] = f2fma(w0, E[j], f2fma(w1, UP[j+1], f2fma(w2, E[j+1], SA[j])));
                }
                if (ky > 0) {
                    const int kb = ky - 1;
                    const ull w0 = pk2(wp[3*kb],   wp[3*kb]);
                    const ull w1 = pk2(wp[3*kb+1], wp[3*kb+1]);
                    const ull w2 = pk2(wp[3*kb+2], wp[3*kb+2]);
                    #pragma unroll
                    for (int j = 0; j < 7; j++)
                        SB[j] = f2fma(w0, E[j], f2fma(w1, UP[j+1], f2fma(w2, E[j+1], SB[j])));
                }
            }

            if ((k & 7) == 0) {
                #pragma unroll
                for (int j = 0; j < 7; j++) {
                    float2 a = up2(SA[j]); mx0[2*j] = a.x; mx0[2*j+1] = a.y;
                    float2 c = up2(SB[j]); mx1[2*j] = c.x; mx1[2*j+1] = c.y;
                }
            } else {
                #pragma unroll
                for (int j = 0; j < 7; j++) {
                    float2 a = up2(SA[j]);
                    mx0[2*j]   = fmaxf(mx0[2*j],   a.x);
                    mx0[2*j+1] = fmaxf(mx0[2*j+1], a.y);
                    float2 c = up2(SB[j]);
                    mx1[2*j]   = fmaxf(mx1[2*j],   c.x);
                    mx1[2*j+1] = fmaxf(mx1[2*j+1], c.y);
                }
            }
            if ((k & 7) == 7) {
                #pragma unroll
                for (int p = 0; p < NPIX; p++) { acc0[p] += mx0[p]; acc1[p] += mx1[p]; }
            }
        }
    }

    if (tid < NACT) {
        float* op = out + ((size_t)(b*OCH + o)*HH + 2*tr)*WW + tx*NPIX;
        #pragma unroll
        for (int p = 0; p < NPIX; p++) op[p]      = acc0[p] * 0.0625f;
        #pragma unroll
        for (int p = 0; p < NPIX; p++) op[WW + p] = acc1[p] * 0.0625f;
    }
}

extern "C" void kernel_launch(void* const* d_in, const int* in_sizes, int n_in,
                              void* d_out, int out_size) {
    const float* x    = (const float*)d_in[0];
    const float* Wt   = (const float*)d_in[1];
    const float* bias = (const float*)d_in[2];
    const void*  idx  = (const void*)d_in[3];
    float* out = (float*)d_out;
    prcn_kernel<<<OCH * 8, NTHR>>>(x, Wt, bias, idx, out);
}

// round 11
// speedup vs baseline: 1.3713x; 1.0475x over previous
#include <cuda_runtime.h>
#include <cstdint>
#include <cstddef>

#define NCH    64
#define OCH    64
#define CONVCH 4096
#define HH     56
#define WW     56
#define PLANE  (HH*WW)     // 3136
#define NPIX   14
#define TROW   58          // full plane + 2 halo rows
#define TCOL   68          // row stride; fill rows 16B aligned; LDS.64 conflict-free
#define NREF   64          // refs per item: one a-half (8 a-groups * 8 g)
#define NTHR   128
#define NACT   112         // 28 row-pairs * 4 col strips
#define NJOB   (HH*14)     // 784 float4 fill jobs
#define OUTN   (8*OCH*PLANE)   // 1,605,632 floats

typedef unsigned long long ull;

// Two channel-half partials per (b,o): scratch[ah][ (b*64+o)*PLANE + px ]
__device__ float g_scratch[2 * OUTN];   // 12.8 MB

__device__ __forceinline__ ull pk2(float lo, float hi) {
    ull r; asm("mov.b64 %0, {%1, %2};" : "=l"(r) : "f"(lo), "f"(hi)); return r;
}
__device__ __forceinline__ float2 up2(ull p) {
    float2 r; asm("mov.b64 {%0, %1}, %2;" : "=f"(r.x), "=f"(r.y) : "l"(p)); return r;
}
__device__ __forceinline__ ull f2fma(ull a, ull b, ull c) {   // packed 2xFMA
    ull d; asm("fma.rn.f32x2 %0, %1, %2, %3;" : "=l"(d) : "l"(a), "l"(b), "l"(c)); return d;
}

__device__ __forceinline__ void cp_async16(void* dst, const void* src) {
    unsigned d = (unsigned)__cvta_generic_to_shared(dst);
    asm volatile("cp.async.cg.shared.global [%0], [%1], 16;\n" :: "r"(d), "l"(src));
}
__device__ __forceinline__ void cp_commit() { asm volatile("cp.async.commit_group;\n" ::: "memory"); }
__device__ __forceinline__ void cp_wait0()  { asm volatile("cp.async.wait_group 0;\n" ::: "memory"); }

__global__ __launch_bounds__(NTHR, 4)
void prcn_kernel(const float* __restrict__ x,
                 const float* __restrict__ Wt,      // [4096,9]
                 const float* __restrict__ bias,    // [4096]
                 const void*  __restrict__ index_raw) // int32 or int64 [8192]
{
    __shared__ float tile[2][TROW][TCOL];   // 31552 B double buffer
    __shared__ ull   wsm2[NREF][10];        // (w,w) pairs: 9 weights + bias
    __shared__ int   cidx[NREF];

    const int tid = threadIdx.x;
    const int ah  = blockIdx.x & 1;          // a-half: refs [64*ah, 64*ah+64)
    const int o   = (blockIdx.x >> 1) & 63;
    const int b   = blockIdx.x >> 7;

    // --- index dtype detection: int32 (JAX x64 off) vs int64 ---
    const int* idx32 = (const int*)index_raw;
    const bool is64 = ((idx32[1] | idx32[3] | idx32[5] | idx32[7]) == 0);

    if (tid < NREF) {
        int j = o*128 + ah*64 + tid;
        int v = is64 ? (int)((const long long*)index_raw)[j] : idx32[j];
        cidx[tid] = v & (CONVCH - 1);
    }
    // Zero both buffers once. Fills rewrite rows 1..56, cols [4,59] every
    // channel; halo rows 0,57 and cols 0..3 / 60..67 stay zero forever.
    for (int j = tid; j < 2*TROW*TCOL; j += NTHR) ((float*)tile)[j] = 0.f;
    __syncthreads();
    for (int j = tid; j < NREF*10; j += NTHR) {
        int k = j / 10, l = j - k*10;
        int c = cidx[k];
        float v = (l < 9) ? Wt[c*9 + l] : bias[c];
        wsm2[k][l] = pk2(v, v);              // pre-duplicated broadcast pair
    }
    __syncthreads();

    // Fill-job geometry: job j -> row rr=j/14, col cc=(j%14)*4.
    int doff[7], soff[7];
    #pragma unroll
    for (int m = 0; m < 7; m++) {
        int j = tid + m*NTHR;
        int rr = j / 14, cc = (j - rr*14) * 4;
        doff[m] = (rr + 1)*TCOL + cc + 4;
        soff[m] = rr*WW + cc;
    }
    const bool job6 = (tid + 6*NTHR) < NJOB;

    const int tr = tid >> 2;        // row-pair index 0..27 (tid < NACT)
    const int tx = tid & 3;
    const int ubase = 14*tx + 2;    // even smem col; u[i] = plane col 14tx-2+i

    // Prologue: fill(0)
    {
        const float* xp = x + (size_t)(b*NCH + (cidx[0] >> 6)) * PLANE;
        float* Tb = &tile[0][0][0];
        #pragma unroll
        for (int m = 0; m < 6; m++) cp_async16(Tb + doff[m], xp + soff[m]);
        if (job6) cp_async16(Tb + doff[6], xp + soff[6]);
        cp_commit();
    }

    float acc0[NPIX], acc1[NPIX], mx0[NPIX], mx1[NPIX];
    #pragma unroll
    for (int p = 0; p < NPIX; p++) { acc0[p] = 0.f; acc1[p] = 0.f; }

    for (int k = 0; k < NREF; k++) {
        cp_wait0();
        __syncthreads();

        if (k + 1 < NREF) {
            const float* xp = x + (size_t)(b*NCH + (cidx[k+1] >> 6)) * PLANE;
            float* Tb = &tile[(k+1) & 1][0][0];
            #pragma unroll
            for (int m = 0; m < 6; m++) cp_async16(Tb + doff[m], xp + soff[m]);
            if (job6) cp_async16(Tb + doff[6], xp + soff[6]);
            cp_commit();
        }

        if (tid < NACT) {
            const ull* wp = wsm2[k];
            const ull BP = wp[9];            // LDS.64 broadcast
            ull SA[7], SB[7];
            #pragma unroll
            for (int j = 0; j < 7; j++) { SA[j] = BP; SB[j] = BP; }

            // 4-row window, pixel-pair packed f32x2 conv.
            // v[i] = u[i+1]; E_j=(hi UP[j], lo UP[j+1]); O_j=UP[j+1].
            #pragma unroll
            for (int ky = 0; ky < 4; ky++) {
                const ull* rp = (const ull*)&tile[k & 1][2*tr + ky][ubase];
                ull UP[9];
                #pragma unroll
                for (int m = 0; m < 9; m++) UP[m] = rp[m];
                ull E[8];
                #pragma unroll
                for (int j = 0; j < 8; j++) {
                    float2 a = up2(UP[j]), c = up2(UP[j+1]);
                    E[j] = pk2(a.y, c.x);
                }
                if (ky < 3) {
                    const ull w0 = wp[3*ky], w1 = wp[3*ky+1], w2 = wp[3*ky+2];
                    #pragma unroll
                    for (int j = 0; j < 7; j++)
                        SA[j] = f2fma(w0, E[j], f2fma(w1, UP[j+1], f2fma(w2, E[j+1], SA[j])));
                }
                if (ky > 0) {
                    const int kb = ky - 1;
                    const ull w0 = wp[3*kb], w1 = wp[3*kb+1], w2 = wp[3*kb+2];
                    #pragma unroll
                    for (int j = 0; j < 7; j++)
                        SB[j] = f2fma(w0, E[j], f2fma(w1, UP[j+1], f2fma(w2, E[j+1], SB[j])));
                }
            }

            if ((k & 7) == 0) {
                #pragma unroll
                for (int j = 0; j < 7; j++) {
                    float2 a = up2(SA[j]); mx0[2*j] = a.x; mx0[2*j+1] = a.y;
                    float2 c = up2(SB[j]); mx1[2*j] = c.x; mx1[2*j+1] = c.y;
                }
            } else {
                #pragma unroll
                for (int j = 0; j < 7; j++) {
                    float2 a = up2(SA[j]);
                    mx0[2*j]   = fmaxf(mx0[2*j],   a.x);
                    mx0[2*j+1] = fmaxf(mx0[2*j+1], a.y);
                    float2 c = up2(SB[j]);
                    mx1[2*j]   = fmaxf(mx1[2*j],   c.x);
                    mx1[2*j+1] = fmaxf(mx1[2*j+1], c.y);
                }
            }
            if ((k & 7) == 7) {
                #pragma unroll
                for (int p = 0; p < NPIX; p++) { acc0[p] += mx0[p]; acc1[p] += mx1[p]; }
            }
        }
    }

    if (tid < NACT) {
        float* sp = g_scratch + (size_t)ah*OUTN
                  + ((size_t)(b*OCH + o)*HH + 2*tr)*WW + tx*NPIX;
        #pragma unroll
        for (int p = 0; p < NPIX; p++) sp[p]      = acc0[p];
        #pragma unroll
        for (int p = 0; p < NPIX; p++) sp[WW + p] = acc1[p];
    }
}

__global__ __launch_bounds__(256)
void combine_kernel(float* __restrict__ out) {
    int j = blockIdx.x * 256 + threadIdx.x;     // float4 index
    if (j < OUTN/4) {
        const float4* s0 = (const float4*)g_scratch;
        const float4* s1 = (const float4*)(g_scratch + OUTN);
        float4 a = s0[j], c = s1[j];
        float4 r;
        r.x = (a.x + c.x) * 0.0625f;
        r.y = (a.y + c.y) * 0.0625f;
        r.z = (a.z + c.z) * 0.0625f;
        r.w = (a.w + c.w) * 0.0625f;
        ((float4*)out)[j] = r;
    }
}

extern "C" void kernel_launch(void* const* d_in, const int* in_sizes, int n_in,
                              void* d_out, int out_size) {
    const float* x    = (const float*)d_in[0];
    const float* Wt   = (const float*)d_in[1];
    const float* bias = (const float*)d_in[2];
    const void*  idx  = (const void*)d_in[3];
    float* out = (float*)d_out;
    prcn_kernel<<<8 * OCH * 2, NTHR>>>(x, Wt, bias, idx);
    combine_kernel<<<(OUTN/4 + 255) / 256, 256>>>(out);
}